// round 17
// baseline (speedup 1.0000x reference)
#include <cuda_runtime.h>
#include <cuda_bf16.h>
#include <math.h>

// ---------------------------------------------------------------------------
// Problem constants
// ---------------------------------------------------------------------------
#define Bsz   4
#define Dd    8
#define Ll    512
#define Hh    768
#define Ff    4096
#define NHEAD 8
#define HD    96         // head dim
#define TOPK  64
#define ROWS  16384      // B*D*L rows of H
#define QS    2304       // fused q|k|v row stride
#define NTOT  12582912LL // 16384*768
#define RES_ROWS 14336   // B*(D-1)*L
#define RES_TOT  11010048LL  // 14336*768
#define Z_TOT    58720256LL  // 14336*4096

#define O_LOSS  0LL
#define O_XHAT  1LL
#define O_NOVEL 11010049LL   // 1 + 11010048
#define O_Z     22020097LL   // 1 + 2*11010048

#define SQRT_HD 9.79795897113271239f   // fp32(sqrt(96)), == sqrtf(96.0f)

// row remap (B,L,D) -> (B,D,L): m = (b*512+l)*8+dd  ->  (b*8+dd)*512+l
__device__ __forceinline__ int permrow(int m)
{
    int b  = m >> 12;          // m / 4096
    int r  = m & 4095;
    int l  = r >> 3;
    int dd = r & 7;
    return (b << 12) | (dd << 9) | l;
}

// ---------------------------------------------------------------------------
// Static device workspace (allocation-free rule: __device__ globals)
// ---------------------------------------------------------------------------
__device__ float g_ln  [NTOT];
__device__ float g_qkv [16384 * 2304];   // fused q|k|v, 151 MB
__device__ float g_wcat[3 * Hh * Hh];    // concatenated Wq|Wk|Wv
__device__ float g_attn[NTOT];
__device__ float g_x   [NTOT];
__device__ float g_sc  [67108864];       // 256 * 512 * 512 scores
__device__ float g_res [RES_TOT];
__device__ float g_z   [Z_TOT];
__device__ float g_dictT[Ff * Hh];
__device__ int   g_tki [RES_ROWS * TOPK];
__device__ float g_tkv [RES_ROWS * TOPK];
__device__ float g_part[3 * RES_ROWS];   // pred | recon | sparse partials

// ---------------------------------------------------------------------------
// LayerNorm: one block per row of 768, 256 threads. Two-pass variance
// (reference's literal mean(square(x - mu))), libdevice rsqrtf, IEEE
// divisions, NO fma contraction in the epilogue. BIT-PATH IS LOAD-BEARING.
// permIn=1: output row r reads source row permrow(r) (replaces perm_fwd).
// ---------------------------------------------------------------------------
__global__ void ln_kernel(const float* __restrict__ x, float* __restrict__ y,
                          const float* __restrict__ gg, const float* __restrict__ bb,
                          int permIn)
{
    int orow = blockIdx.x;
    long long srow = permIn ? permrow(orow) : orow;
    const float* xr = x + srow * (long long)Hh;
    float* yr = y + (long long)orow * Hh;
    int t = threadIdx.x;
    float v0 = xr[t], v1 = xr[t + 256], v2 = xr[t + 512];
    __shared__ float sa[8], sq[8];

    float s = __fadd_rn(__fadd_rn(v0, v1), v2);
    #pragma unroll
    for (int o = 16; o; o >>= 1) s += __shfl_xor_sync(0xffffffffu, s, o);
    if ((t & 31) == 0) sa[t >> 5] = s;
    __syncthreads();
    s = 0.f;
    #pragma unroll
    for (int w = 0; w < 8; w++) s += sa[w];
    float mu = __fdiv_rn(s, 768.0f);

    float d0 = __fsub_rn(v0, mu), d1 = __fsub_rn(v1, mu), d2 = __fsub_rn(v2, mu);
    float s2 = __fadd_rn(__fadd_rn(__fmul_rn(d0, d0), __fmul_rn(d1, d1)), __fmul_rn(d2, d2));
    #pragma unroll
    for (int o = 16; o; o >>= 1) s2 += __shfl_xor_sync(0xffffffffu, s2, o);
    if ((t & 31) == 0) sq[t >> 5] = s2;
    __syncthreads();
    s2 = 0.f;
    #pragma unroll
    for (int w = 0; w < 8; w++) s2 += sq[w];
    float var  = __fdiv_rn(s2, 768.0f);
    float rstd = rsqrtf(__fadd_rn(var, 1e-5f));

    yr[t]       = __fadd_rn(__fmul_rn(__fmul_rn(d0, rstd), gg[t]),       bb[t]);
    yr[t + 256] = __fadd_rn(__fmul_rn(__fmul_rn(d1, rstd), gg[t + 256]), bb[t + 256]);
    yr[t + 512] = __fadd_rn(__fmul_rn(__fmul_rn(d2, rstd), gg[t + 512]), bb[t + 512]);
}

// ---------------------------------------------------------------------------
// Tiled SGEMM, STRICT k-ascending fp32 FMA accumulation per output element.
// Per-element rounding chain identical to R9 (correlated with the reference
// GEMM — protects the top-k boundary). DO NOT alter the order.
//
// R16: BM=128, BN=64, BK=32, 128 threads, 8x8 fragment, conflict-free smem
// schedule, DOUBLE-BUFFERED with staged in-loop copy: next tile's LDGs are
// issued between 8-k compute blocks (each LDG gets >=512 FFMA-cycles before
// its dependent STS), one barrier per tile. Removes exposed load latency —
// the bubble source R14/R15 only amortized.
//   TRANSB=true : C[M,N] = A[M,K] * B[N,K]^T
//   TRANSB=false: C[M,N] = A[M,K] * B[K,N]
// Requires M % 128 == 0, K % 32 == 0; N guarded at float4 grain.
// ---------------------------------------------------------------------------
template<bool TRANSB>
__global__ void __launch_bounds__(128, 4)
sgemm_kernel(const float* __restrict__ Ag, const float* __restrict__ Bg,
             float* __restrict__ Cg,
             const float* __restrict__ addsrc, const float* __restrict__ bias,
             int M, int N, int K, int lda, int ldb, int ldc,
             long long sA1, long long sA2, long long sB1, long long sB2,
             long long sC1, long long sC2, int bdiv,
             int relu, int permRows)
{
    int z  = blockIdx.z;
    int z1 = z / bdiv, z2 = z - z1 * bdiv;
    const float* A = Ag + z1 * sA1 + z2 * sA2;
    const float* B = Bg + z1 * sB1 + z2 * sB2;
    float*       C = Cg + z1 * sC1 + z2 * sC2;
    const float* add = addsrc ? (addsrc + z1 * sC1 + z2 * sC2) : (const float*)0;

    __shared__ float As[2][32][128];   // 32 KB
    __shared__ float Bs[2][32][64];    // 16 KB  (total 48 KB = static cap)

    int m0 = blockIdx.y * 128;
    int n0 = blockIdx.x * 64;
    int t  = threadIdx.x;          // 128 threads
    int tx = t & 7, ty = t >> 3;   // fragment grid

    // per-thread load coordinates
    const float* Arow = A + (long long)(m0 + t) * lda;   // A: row m0+t, k-strip
    // B (transB): i = t + r*128 -> n = i&63, kq = i>>6 (r=0..3)
    // B (k-major): i = t + r*128 -> rk = i>>4, nq = i&15

    float acc[8][8];
    #pragma unroll
    for (int i = 0; i < 8; i++)
        #pragma unroll
        for (int j = 0; j < 8; j++) acc[i][j] = 0.f;

    // ---- staged loaders ----
    // A half h (h=0,1): 4 float4 = k [h*16, h*16+16)
    #define LDA_H(ra, kb, h)                                                 \
        { _Pragma("unroll")                                                  \
          for (int r = 0; r < 4; r++)                                        \
              ra[r] = *(const float4*)(Arow + (kb) + (h)*16 + r*4); }
    #define STA_H(nb, ra, h)                                                 \
        { _Pragma("unroll")                                                  \
          for (int r = 0; r < 4; r++) {                                      \
              As[nb][(h)*16 + r*4 + 0][t] = ra[r].x;                         \
              As[nb][(h)*16 + r*4 + 1][t] = ra[r].y;                         \
              As[nb][(h)*16 + r*4 + 2][t] = ra[r].z;                         \
              As[nb][(h)*16 + r*4 + 3][t] = ra[r].w; } }
    // B full tile: 4 float4
    #define LDB_F(rb, kb)                                                    \
        { _Pragma("unroll")                                                  \
          for (int r = 0; r < 4; r++) {                                      \
              int i = t + r * 128;                                           \
              rb[r] = make_float4(0.f, 0.f, 0.f, 0.f);                       \
              if (TRANSB) {                                                  \
                  int n = i & 63, kq = i >> 6;                               \
                  if (n0 + n < N)                                            \
                      rb[r] = *(const float4*)(B + (long long)(n0 + n) * ldb \
                                               + (kb) + kq * 4);             \
              } else {                                                       \
                  int rk = i >> 4, nq = i & 15;                              \
                  if (n0 + nq * 4 < N)                                       \
                      rb[r] = *(const float4*)(B + (long long)((kb) + rk) * ldb \
                                               + (n0 + nq * 4));             \
              } } }
    #define STB_F(nb, rb)                                                    \
        { _Pragma("unroll")                                                  \
          for (int r = 0; r < 4; r++) {                                      \
              int i = t + r * 128;                                           \
              if (TRANSB) {                                                  \
                  int n = i & 63, kq = i >> 6;                               \
                  Bs[nb][kq*4+0][n] = rb[r].x;                               \
                  Bs[nb][kq*4+1][n] = rb[r].y;                               \
                  Bs[nb][kq*4+2][n] = rb[r].z;                               \
                  Bs[nb][kq*4+3][n] = rb[r].w;                               \
              } else {                                                       \
                  int rk = i >> 4, nq = i & 15;                              \
                  *(float4*)&Bs[nb][rk][nq * 4] = rb[r];                     \
              } } }
    // 8 consecutive k of compute on buffer bf starting at k-index k8
    #define C8(bf, k8)                                                       \
        { _Pragma("unroll")                                                  \
          for (int kk = 0; kk < 8; kk++) {                                   \
              int k = (k8) + kk;                                             \
              float a[8], b[8];                                              \
              *(float4*)&a[0] = *(const float4*)&As[bf][k][ty * 8];          \
              *(float4*)&a[4] = *(const float4*)&As[bf][k][ty * 8 + 4];      \
              *(float4*)&b[0] = *(const float4*)&Bs[bf][k][tx * 4];          \
              *(float4*)&b[4] = *(const float4*)&Bs[bf][k][tx * 4 + 32];     \
              _Pragma("unroll")                                              \
              for (int i = 0; i < 8; i++)                                    \
                  _Pragma("unroll")                                          \
                  for (int j = 0; j < 8; j++)                                \
                      acc[i][j] += a[i] * b[j]; } }   /* FFMA, strict k */

    // ---- prologue: fill buffer 0 with tile 0 ----
    {
        float4 ra[4], rb[4];
        LDA_H(ra, 0, 0); STA_H(0, ra, 0);
        LDA_H(ra, 0, 1); STA_H(0, ra, 1);
        LDB_F(rb, 0);    STB_F(0, rb);
    }
    __syncthreads();

    int nt = K >> 5;
    for (int ti = 0; ti < nt; ti++) {
        int cur = ti & 1, nxt = cur ^ 1;
        int kn  = (ti + 1) << 5;
        bool last = (ti == nt - 1);
        float4 ra[4], rb[4];

        C8(cur, 0);
        if (!last) { LDA_H(ra, kn, 0); }
        C8(cur, 8);
        if (!last) { STA_H(nxt, ra, 0); LDB_F(rb, kn); }
        C8(cur, 16);
        if (!last) { STB_F(nxt, rb); LDA_H(ra, kn, 1); }
        C8(cur, 24);
        if (!last) { STA_H(nxt, ra, 1); }
        __syncthreads();
    }

    #undef LDA_H
    #undef STA_H
    #undef LDB_F
    #undef STB_F
    #undef C8

    // ---- epilogue: 8 rows x 2 float4 per thread (split columns) ----
    #pragma unroll
    for (int i = 0; i < 8; i++) {
        int  mi = m0 + ty * 8 + i;
        long long m = permRows ? permrow(mi) : mi;
        #pragma unroll
        for (int q = 0; q < 2; q++) {
            int n = n0 + q * 32 + tx * 4;
            if (n < N) {
                float4 r;
                r.x = acc[i][q*4+0]; r.y = acc[i][q*4+1];
                r.z = acc[i][q*4+2]; r.w = acc[i][q*4+3];
                if (bias) {
                    r.x = __fadd_rn(r.x, bias[n]);   r.y = __fadd_rn(r.y, bias[n+1]);
                    r.z = __fadd_rn(r.z, bias[n+2]); r.w = __fadd_rn(r.w, bias[n+3]);
                }
                if (add) {
                    float4 a4 = *(const float4*)(add + m * ldc + n);
                    r.x = __fadd_rn(r.x, a4.x); r.y = __fadd_rn(r.y, a4.y);
                    r.z = __fadd_rn(r.z, a4.z); r.w = __fadd_rn(r.w, a4.w);
                }
                if (relu) {
                    r.x = fmaxf(r.x, 0.f); r.y = fmaxf(r.y, 0.f);
                    r.z = fmaxf(r.z, 0.f); r.w = fmaxf(r.w, 0.f);
                }
                *(float4*)(C + m * ldc + n) = r;
            }
        }
    }
}

// ---------------------------------------------------------------------------
// Row softmax over 512 (non-causal), in place. One block (128 thr) per row.
// IEEE div by sqrt(96), libdevice expf, IEEE normalize. BIT-PATH LOAD-BEARING.
// ---------------------------------------------------------------------------
__global__ void softmax512_kernel(float* __restrict__ sc)
{
    long long row = blockIdx.x;
    float* p = sc + row * 512;
    int t = threadIdx.x;
    float v[4];
    #pragma unroll
    for (int i = 0; i < 4; i++) v[i] = __fdiv_rn(p[t + i * 128], SQRT_HD);
    float m = fmaxf(fmaxf(v[0], v[1]), fmaxf(v[2], v[3]));
    __shared__ float sm[4], ss[4];
    #pragma unroll
    for (int o = 16; o; o >>= 1) m = fmaxf(m, __shfl_xor_sync(0xffffffffu, m, o));
    if ((t & 31) == 0) sm[t >> 5] = m;
    __syncthreads();
    m = fmaxf(fmaxf(sm[0], sm[1]), fmaxf(sm[2], sm[3]));
    float s = 0.f;
    #pragma unroll
    for (int i = 0; i < 4; i++) { v[i] = expf(__fsub_rn(v[i], m)); s += v[i]; }
    #pragma unroll
    for (int o = 16; o; o >>= 1) s += __shfl_xor_sync(0xffffffffu, s, o);
    if ((t & 31) == 0) ss[t >> 5] = s;
    __syncthreads();
    s = ss[0] + ss[1] + ss[2] + ss[3];
    #pragma unroll
    for (int i = 0; i < 4; i++) p[t + i * 128] = __fdiv_rn(v[i], s);
}

// ---------------------------------------------------------------------------
// Tiny causal attention over depth (D=8 tokens), reading the fused qkv
// buffer (row stride QS, q at +0, k at +768, v at +1536).
// ---------------------------------------------------------------------------
__global__ void attn2_kernel(const float* __restrict__ qkv, float* __restrict__ o)
{
    int bl = blockIdx.x;   // 0..2047 = b*512+l
    int h  = blockIdx.y;   // 0..7
    int t  = threadIdx.x;  // 128
    __shared__ float qs[8][97], ks[8][97], vs[8][97], ps[8][8];
    long long qbase = (long long)bl * 8 * QS + h * HD;
    long long obase = (long long)bl * 8 * Hh + h * HD;
    if (t < 96) {
        #pragma unroll
        for (int tok = 0; tok < 8; tok++) {
            qs[tok][t] = qkv[qbase + tok * QS + t];
            ks[tok][t] = qkv[qbase + 768 + tok * QS + t];
            vs[tok][t] = qkv[qbase + 1536 + tok * QS + t];
        }
    }
    __syncthreads();
    if (t < 64) {
        int t1 = t >> 3, t2 = t & 7;
        float s = -1e30f;
        if (t2 <= t1) {
            float a = 0.f;
            #pragma unroll 8
            for (int d2 = 0; d2 < 96; d2++) a += qs[t1][d2] * ks[t2][d2];  // FFMA, d ascending
            s = __fdiv_rn(a, SQRT_HD);
        }
        float m = s;
        #pragma unroll
        for (int o2 = 1; o2 <= 4; o2 <<= 1) m = fmaxf(m, __shfl_xor_sync(0xffffffffu, m, o2));
        float e = (t2 <= t1) ? expf(__fsub_rn(s, m)) : 0.0f;
        float sum = e;
        #pragma unroll
        for (int o2 = 1; o2 <= 4; o2 <<= 1) sum += __shfl_xor_sync(0xffffffffu, sum, o2);
        ps[t1][t2] = __fdiv_rn(e, sum);
    }
    __syncthreads();
    if (t < 96) {
        #pragma unroll
        for (int t1 = 0; t1 < 8; t1++) {
            float a = 0.f;
            #pragma unroll
            for (int t2 = 0; t2 < 8; t2++) a += ps[t1][t2] * vs[t2][t];    // FFMA, m ascending
            o[obase + t1 * Hh + t] = a;
        }
    }
}

// ---------------------------------------------------------------------------
// Dictionary transpose: (768,4096) -> (4096,768)
// ---------------------------------------------------------------------------
__global__ void transpose_dict_kernel(const float* __restrict__ in, float* __restrict__ out)
{
    __shared__ float tile[32][33];
    int bx = blockIdx.x * 32;   // F dir
    int by = blockIdx.y * 32;   // H dir
    int x = threadIdx.x, y = threadIdx.y;
    #pragma unroll
    for (int j = 0; j < 32; j += 8)
        tile[y + j][x] = in[(long long)(by + y + j) * Ff + bx + x];
    __syncthreads();
    #pragma unroll
    for (int j = 0; j < 32; j += 8)
        out[(long long)(bx + y + j) * Hh + by + x] = tile[x][y + j];
}

// ---------------------------------------------------------------------------
// residual = x[:,1:] - x[:,:-1]  (row-major (B,7,L,H))
// ---------------------------------------------------------------------------
__global__ void res_kernel(const float* __restrict__ x, float* __restrict__ res)
{
    long long i = (long long)blockIdx.x * 256 + threadIdx.x;
    if (i >= RES_TOT) return;
    int h = (int)(i % Hh);
    long long r = i / Hh;
    int l = (int)(r % Ll);
    long long bd = r / Ll;
    int dd = (int)(bd % 7);
    int b  = (int)(bd / 7);
    long long i0 = ((long long)(b * Dd + dd) * Ll + l) * Hh + h;
    res[i] = __fsub_rn(x[i0 + (long long)Ll * Hh], x[i0]);
}

// ---------------------------------------------------------------------------
// Top-64 per row of 4096 via 4-pass radix select on the (monotone, >=0)
// float bit patterns. Selection set IDENTICAL to jax.lax.top_k semantics.
// Deterministic index-ascending compaction. Writes z_n into d_out + L1 sum.
// ---------------------------------------------------------------------------
__global__ void topk_kernel(const float* __restrict__ z, float* __restrict__ out,
                            int* __restrict__ tki, float* __restrict__ tkv,
                            float* __restrict__ sparse_part)
{
    long long row = blockIdx.x;
    const float* zr = z + row * Ff;
    __shared__ float rS[Ff];
    __shared__ unsigned char sS[Ff];
    __shared__ int hist[256];
    __shared__ int tmp[256];
    __shared__ unsigned int sPrefix;
    __shared__ int sRem, sB, sRemNext;
    int t = threadIdx.x;          // 256 threads

    for (int i = t; i < Ff; i += 256) rS[i] = zr[i];
    if (t == 0) { sPrefix = 0u; sRem = TOPK; }
    __syncthreads();

    #pragma unroll
    for (int shift = 24; shift >= 0; shift -= 8) {
        hist[t] = 0;
        __syncthreads();
        unsigned int mask = (shift == 24) ? 0u : (0xFFFFFFFFu << (shift + 8));
        unsigned int pfx  = sPrefix;
        for (int i = t; i < Ff; i += 256) {
            unsigned int u = __float_as_uint(rS[i]);
            if ((u & mask) == pfx) atomicAdd(&hist[(u >> shift) & 255], 1);
        }
        __syncthreads();
        int v = hist[255 - t];
        tmp[t] = v;
        __syncthreads();
        for (int off = 1; off < 256; off <<= 1) {
            int x = (t >= off) ? tmp[t - off] : 0;
            __syncthreads();
            tmp[t] += x;
            __syncthreads();
        }
        int rem  = sRem;
        int sfx  = tmp[t];
        int sfx1 = (t == 0) ? 0 : tmp[t - 1];
        if (sfx >= rem && sfx1 < rem) {
            sB = 255 - t;
            sRemNext = rem - sfx1;
        }
        __syncthreads();
        if (t == 0) {
            sPrefix |= ((unsigned int)sB) << shift;
            sRem = sRemNext;
        }
        __syncthreads();
    }
    unsigned int T = sPrefix;
    int rtake = sRem;

    int base = t * 16;
    int cntEq = 0;
    #pragma unroll
    for (int j = 0; j < 16; j++)
        if (__float_as_uint(rS[base + j]) == T) cntEq++;
    __syncthreads();
    tmp[t] = cntEq;
    __syncthreads();
    for (int off = 1; off < 256; off <<= 1) {
        int x = (t >= off) ? tmp[t - off] : 0;
        __syncthreads();
        tmp[t] += x;
        __syncthreads();
    }
    int eqRank = tmp[t] - cntEq;
    int cntSel = 0;
    #pragma unroll
    for (int j = 0; j < 16; j++) {
        unsigned int u = __float_as_uint(rS[base + j]);
        bool sel;
        if (u > T)       sel = true;
        else if (u == T) { sel = (eqRank < rtake); eqRank++; }
        else             sel = false;
        sS[base + j] = sel ? 1 : 0;
        cntSel += sel ? 1 : 0;
    }
    __syncthreads();
    tmp[t] = cntSel;
    __syncthreads();
    for (int off = 1; off < 256; off <<= 1) {
        int x = (t >= off) ? tmp[t - off] : 0;
        __syncthreads();
        tmp[t] += x;
        __syncthreads();
    }
    int pos = tmp[t] - cntSel;
    #pragma unroll
    for (int j = 0; j < 16; j++) {
        if (sS[base + j]) {
            tki[row * TOPK + pos] = base + j;
            tkv[row * TOPK + pos] = rS[base + j];
            pos++;
        }
    }
    __syncthreads();

    float ls = 0.f;
    long long ob = O_Z + row * Ff;
    for (int i = t; i < Ff; i += 256) {
        float vv = sS[i] ? rS[i] : 0.0f;
        out[ob + i] = vv;
        ls += vv;
    }
    __shared__ float sp[8];
    #pragma unroll
    for (int o = 16; o; o >>= 1) ls += __shfl_xor_sync(0xffffffffu, ls, o);
    if ((t & 31) == 0) sp[t >> 5] = ls;
    __syncthreads();
    if (t == 0) {
        float s = 0.f;
        #pragma unroll
        for (int w = 0; w < 8; w++) s += sp[w];
        sparse_part[row] = s;
    }
}

// ---------------------------------------------------------------------------
// Sparse decode: x_novel = sum_j z_j * dictT[j], fused with x_hat and
// per-row pred/recon loss partials. Block per row (256 threads, 3 dims each).
// ---------------------------------------------------------------------------
__global__ void novel_kernel(const float* __restrict__ dictT, const float* __restrict__ x,
                             const int* __restrict__ tki, const float* __restrict__ tkv,
                             float* __restrict__ out,
                             float* __restrict__ pred_part, float* __restrict__ recon_part)
{
    long long row = blockIdx.x;     // (b*7+dd)*512 + l
    int t = threadIdx.x;
    __shared__ int   sI[TOPK];
    __shared__ float sV[TOPK];
    if (t < TOPK) { sI[t] = tki[row * TOPK + t]; sV[t] = tkv[row * TOPK + t]; }
    __syncthreads();

    int l = (int)(row % Ll);
    long long bd = row / Ll;
    int dd = (int)(bd % 7);
    int b  = (int)(bd / 7);
    const float* xp = x + ((long long)(b * Dd + dd)     * Ll + l) * Hh;
    const float* xt = x + ((long long)(b * Dd + dd + 1) * Ll + l) * Hh;

    float a0 = 0.f, a1 = 0.f, a2 = 0.f;
    #pragma unroll 4
    for (int j = 0; j < TOPK; j++) {
        float vv = sV[j];
        const float* dr = dictT + (long long)sI[j] * Hh;
        a0 += vv * dr[t];
        a1 += vv * dr[t + 256];
        a2 += vv * dr[t + 512];
    }

    float lr = 0.f, lp = 0.f;
    long long ob = row * Hh;
    float nv[3] = { a0, a1, a2 };
    #pragma unroll
    for (int i = 0; i < 3; i++) {
        int h = t + i * 256;
        float px = xp[h], tg = xt[h];
        float nov = nv[i];
        float xh = __fadd_rn(px, nov);
        out[O_NOVEL + ob + h] = nov;
        out[O_XHAT  + ob + h] = xh;
        float d1 = __fsub_rn(xh, tg); lr += d1 * d1;
        float d2 = __fsub_rn(tg, px); lp += d2 * d2;
    }
    __shared__ float s1[8], s2[8];
    #pragma unroll
    for (int o = 16; o; o >>= 1) {
        lr += __shfl_xor_sync(0xffffffffu, lr, o);
        lp += __shfl_xor_sync(0xffffffffu, lp, o);
    }
    if ((t & 31) == 0) { s1[t >> 5] = lr; s2[t >> 5] = lp; }
    __syncthreads();
    if (t == 0) {
        float r = 0.f, p = 0.f;
        #pragma unroll
        for (int w = 0; w < 8; w++) { r += s1[w]; p += s2[w]; }
        recon_part[row] = r;
        pred_part[row]  = p;
    }
}

// ---------------------------------------------------------------------------
// Final deterministic loss reduction
// ---------------------------------------------------------------------------
__global__ void loss_kernel(const float* __restrict__ pred_part,
                            const float* __restrict__ recon_part,
                            const float* __restrict__ sparse_part,
                            float* __restrict__ out)
{
    int t = threadIdx.x;   // 256
    double sp = 0.0, sr = 0.0, ss = 0.0;
    for (int i = t; i < RES_ROWS; i += 256) {
        sp += (double)pred_part[i];
        sr += (double)recon_part[i];
        ss += (double)sparse_part[i];
    }
    __shared__ double da[256], db[256], dc[256];
    da[t] = sp; db[t] = sr; dc[t] = ss;
    __syncthreads();
    for (int o = 128; o; o >>= 1) {
        if (t < o) { da[t] += da[t + o]; db[t] += db[t + o]; dc[t] += dc[t + o]; }
        __syncthreads();
    }
    if (t == 0) {
        double loss = da[0] / 11010048.0 + db[0] / 11010048.0 + 0.001 * (dc[0] / 58720256.0);
        out[O_LOSS] = (float)loss;
    }
}

// ---------------------------------------------------------------------------
// Host side
// ---------------------------------------------------------------------------
static void sgemm(bool transB, const float* A, const float* B, float* C,
                  const float* add, const float* bias,
                  int M, int N, int K, int lda, int ldb, int ldc,
                  long long sA1, long long sA2, long long sB1, long long sB2,
                  long long sC1, long long sC2, int bdiv, int batch,
                  int relu, int permRows)
{
    dim3 grid((N + 63) / 64, M / 128, batch);
    if (transB)
        sgemm_kernel<true><<<grid, 128>>>(A, B, C, add, bias, M, N, K, lda, ldb, ldc,
                                          sA1, sA2, sB1, sB2, sC1, sC2, bdiv, relu, permRows);
    else
        sgemm_kernel<false><<<grid, 128>>>(A, B, C, add, bias, M, N, K, lda, ldb, ldc,
                                           sA1, sA2, sB1, sB2, sC1, sC2, bdiv, relu, permRows);
}

extern "C" void kernel_launch(void* const* d_in, const int* in_sizes, int n_in,
                              void* d_out, int out_size)
{
    const float* zL    = (const float*)d_in[0];
    const float* Wq_l  = (const float*)d_in[1];
    const float* Wk_l  = (const float*)d_in[2];
    const float* Wv_l  = (const float*)d_in[3];
    const float* Wo_l  = (const float*)d_in[4];
    const float* gl    = (const float*)d_in[5];
    const float* bl    = (const float*)d_in[6];
    const float* Wq_d  = (const float*)d_in[7];
    const float* Wk_d  = (const float*)d_in[8];
    const float* Wv_d  = (const float*)d_in[9];
    const float* Wo_d  = (const float*)d_in[10];
    const float* gd    = (const float*)d_in[11];
    const float* bd    = (const float*)d_in[12];
    const float* dict  = (const float*)d_in[13];
    const float* biasn = (const float*)d_in[14];
    float* out = (float*)d_out;

    float *p_ln, *p_qkv, *p_wcat, *p_attn, *p_x, *p_sc, *p_res, *p_z, *p_dT, *p_tkv, *p_part;
    int *p_tki;
    cudaGetSymbolAddress((void**)&p_ln,   g_ln);
    cudaGetSymbolAddress((void**)&p_qkv,  g_qkv);
    cudaGetSymbolAddress((void**)&p_wcat, g_wcat);
    cudaGetSymbolAddress((void**)&p_attn, g_attn);
    cudaGetSymbolAddress((void**)&p_x,    g_x);
    cudaGetSymbolAddress((void**)&p_sc,   g_sc);
    cudaGetSymbolAddress((void**)&p_res,  g_res);
    cudaGetSymbolAddress((void**)&p_z,    g_z);
    cudaGetSymbolAddress((void**)&p_dT,   g_dictT);
    cudaGetSymbolAddress((void**)&p_tki,  g_tki);
    cudaGetSymbolAddress((void**)&p_tkv,  g_tkv);
    cudaGetSymbolAddress((void**)&p_part, g_part);

    const long long SQH  = (long long)Ll * Hh;   // 512*768 seq stride (attn buf)
    const long long SQQ  = (long long)Ll * QS;   // 512*2304 seq stride (qkv buf)
    const long long SCB  = (long long)Ll * Ll;   // per-head score size
    const size_t WBYTES  = (size_t)Hh * Hh * sizeof(float);

    // ---------------- Stage A: attention over L (non-causal) ----------------
    ln_kernel<<<ROWS, 256>>>(zL, p_ln, gl, bl, 0);
    cudaMemcpyAsync(p_wcat,             Wq_l, WBYTES, cudaMemcpyDeviceToDevice);
    cudaMemcpyAsync(p_wcat + Hh * Hh,   Wk_l, WBYTES, cudaMemcpyDeviceToDevice);
    cudaMemcpyAsync(p_wcat + 2*Hh*Hh,   Wv_l, WBYTES, cudaMemcpyDeviceToDevice);
    sgemm(true, p_ln, p_wcat, p_qkv, 0, 0, ROWS, QS, Hh, Hh, Hh, QS,
          0,0,0,0,0,0, 1, 1, 0, 0);
    // raw scores (K=96 -> 3 tiles)
    sgemm(true, p_qkv, p_qkv + 768, p_sc, 0, 0, Ll, Ll, HD, QS, QS, Ll,
          SQQ, HD, SQQ, HD, 8*SCB, SCB, NHEAD, 32*NHEAD, 0, 0);
    softmax512_kernel<<<131072, 128>>>(p_sc);
    // attn = P V
    sgemm(false, p_sc, p_qkv + 1536, p_attn, 0, 0, Ll, HD, Ll, Ll, QS, Hh,
          8*SCB, SCB, SQQ, HD, SQH, HD, NHEAD, 32*NHEAD, 0, 0);
    // x = zL + attn Wo^T
    sgemm(true, p_attn, Wo_l, p_x, zL, 0, ROWS, Hh, Hh, Hh, Hh, Hh,
          0,0,0,0,0,0, 1, 1, 0, 0);

    // ---------------- Stage B: causal attention over depth D ----------------
    // ln reads p_x with row remap (replaces perm_fwd); outputs (B,L,D) layout
    ln_kernel<<<ROWS, 256>>>(p_x, p_ln, gd, bd, 1);
    cudaMemcpyAsync(p_wcat,             Wq_d, WBYTES, cudaMemcpyDeviceToDevice);
    cudaMemcpyAsync(p_wcat + Hh * Hh,   Wk_d, WBYTES, cudaMemcpyDeviceToDevice);
    cudaMemcpyAsync(p_wcat + 2*Hh*Hh,   Wv_d, WBYTES, cudaMemcpyDeviceToDevice);
    sgemm(true, p_ln, p_wcat, p_qkv, 0, 0, ROWS, QS, Hh, Hh, Hh, QS,
          0,0,0,0,0,0, 1, 1, 0, 0);
    attn2_kernel<<<dim3(2048, NHEAD), 128>>>(p_qkv, p_attn);
    // x = x + attn Wo^T with row-remapped add/C (replaces perm_bwd)
    sgemm(true, p_attn, Wo_d, p_x, p_x, 0, ROWS, Hh, Hh, Hh, Hh, Hh,
          0,0,0,0,0,0, 1, 1, 0, 1);

    // ---------------- SAE head ----------------
    transpose_dict_kernel<<<dim3(128, 24), dim3(32, 8)>>>(dict, p_dT);
    res_kernel<<<43008, 256>>>(p_x, p_res);
    // z_dense = relu(res @ dict + bias)
    sgemm(false, p_res, dict, p_z, 0, biasn, RES_ROWS, Ff, Hh, Hh, Ff, Ff,
          0,0,0,0,0,0, 1, 1, 1, 0);
    topk_kernel<<<RES_ROWS, 256>>>(p_z, out, p_tki, p_tkv, p_part + 2 * RES_ROWS);
    novel_kernel<<<RES_ROWS, 256>>>(p_dT, p_x, p_tki, p_tkv, out,
                                    p_part, p_part + RES_ROWS);
    loss_kernel<<<1, 256>>>(p_part, p_part + RES_ROWS, p_part + 2 * RES_ROWS, out);
}